// round 11
// baseline (speedup 1.0000x reference)
#include <cuda_runtime.h>
#include <cuda_bf16.h>
#include <cstdint>
#include <math.h>

#define B_  2
#define S_  2048
#define H_  4096
#define NH_ 32
#define HD_ 128
#define T_  (B_*S_)    // 4096 tokens
#define N3_ (3*H_)     // 12288

// ---------------- scratch (__device__ globals; no allocation allowed) -------
__device__ __nv_bfloat16 g_Qhi[(size_t)B_*NH_*S_*HD_];  // [bh][s][d] split
__device__ __nv_bfloat16 g_Qlo[(size_t)B_*NH_*S_*HD_];
__device__ __nv_bfloat16 g_Khi[(size_t)B_*NH_*S_*HD_];
__device__ __nv_bfloat16 g_Klo[(size_t)B_*NH_*S_*HD_];
__device__ __nv_bfloat16 g_Vhi[(size_t)B_*NH_*S_*HD_];
__device__ __nv_bfloat16 g_Vlo[(size_t)B_*NH_*S_*HD_];

__device__ __nv_bfloat16 g_Ahi[(size_t)T_*H_];     // hidden split
__device__ __nv_bfloat16 g_Alo[(size_t)T_*H_];
__device__ __nv_bfloat16 g_Whi[(size_t)N3_*H_];    // w_attn split
__device__ __nv_bfloat16 g_Wlo[(size_t)N3_*H_];
__device__ __nv_bfloat16 g_Phi[(size_t)H_*H_];     // w_proj split
__device__ __nv_bfloat16 g_Plo[(size_t)H_*H_];
__device__ __nv_bfloat16 g_Chi[(size_t)T_*H_];     // ctx split (attn output)
__device__ __nv_bfloat16 g_Clo[(size_t)T_*H_];

// ---------------- helpers ---------------------------------------------------
__device__ __forceinline__ uint32_t smem_u32(const void* p) {
    uint32_t a;
    asm("{ .reg .u64 t; cvta.to.shared.u64 t, %1; cvt.u32.u64 %0, t; }" : "=r"(a) : "l"(p));
    return a;
}
__device__ __forceinline__ uint32_t swz(uint32_t o) { return o ^ ((o >> 3) & 0x70); }

__device__ __forceinline__ void cp16(uint32_t dst, const void* src) {
    asm volatile("cp.async.cg.shared.global [%0], [%1], 16;" :: "r"(dst), "l"(src));
}
__device__ __forceinline__ void ldmx4(uint32_t* r, uint32_t addr) {
    asm volatile("ldmatrix.sync.aligned.m8n8.x4.shared.b16 {%0,%1,%2,%3}, [%4];"
        : "=r"(r[0]), "=r"(r[1]), "=r"(r[2]), "=r"(r[3]) : "r"(addr));
}
__device__ __forceinline__ void ldmx4t(uint32_t* r, uint32_t addr) {
    asm volatile("ldmatrix.sync.aligned.m8n8.x4.trans.shared.b16 {%0,%1,%2,%3}, [%4];"
        : "=r"(r[0]), "=r"(r[1]), "=r"(r[2]), "=r"(r[3]) : "r"(addr));
}
__device__ __forceinline__ void mma16816(float* c, const uint32_t* a, const uint32_t* b) {
    asm volatile("mma.sync.aligned.m16n8k16.row.col.f32.bf16.bf16.f32 "
        "{%0,%1,%2,%3}, {%4,%5,%6,%7}, {%8,%9}, {%0,%1,%2,%3};"
        : "+f"(c[0]), "+f"(c[1]), "+f"(c[2]), "+f"(c[3])
        : "r"(a[0]), "r"(a[1]), "r"(a[2]), "r"(a[3]), "r"(b[0]), "r"(b[1]));
}
__device__ __forceinline__ uint32_t pack_bf2(float x, float y) {
    __nv_bfloat162 t = __floats2bfloat162_rn(x, y);
    return *(uint32_t*)&t;
}
__device__ __forceinline__ void split_store(__nv_bfloat16* hi, __nv_bfloat16* lo,
                                            size_t off, float x, float y) {
    __nv_bfloat16 hx = __float2bfloat16(x), hy = __float2bfloat16(y);
    *(__nv_bfloat162*)(hi + off) = __nv_bfloat162(hx, hy);
    *(__nv_bfloat162*)(lo + off) = __nv_bfloat162(
        __float2bfloat16(x - __bfloat162float(hx)),
        __float2bfloat16(y - __bfloat162float(hy)));
}

// ---------------------------------------------------------------------------
// fp32 -> (hi, lo) bf16 split
// ---------------------------------------------------------------------------
__global__ __launch_bounds__(256) void f32_split(
    const float* __restrict__ x, __nv_bfloat16* __restrict__ hi,
    __nv_bfloat16* __restrict__ lo, int n)
{
    int i = (blockIdx.x * 256 + threadIdx.x) * 4;
    if (i >= n) return;
    float4 v = *(const float4*)(x + i);
    split_store(hi, lo, i, v.x, v.y);
    split_store(hi, lo, i + 2, v.z, v.w);
}

// ---------------------------------------------------------------------------
// mma.sync split-bf16 GEMM: C[M,N] = A[M,K] @ B[N,K]^T   (3-term split)
// BM=128, BN=128, BK=64, 3 buffers / prefetch-distance-2 cp.async pipeline,
// 256 threads / 8 warps (warp = 16m x 128n).  ONE __syncthreads per chunk:
//   wait_group 1 (chunk it ready) -> sync -> issue loads it+2 into buffer
//   (it+2)%3 (last read at iter it-1) -> MMA on buffer it%3.
// mode 0: QKV epilogue (bias+RoPE+logn -> split-bf16 Q/K/V),  mode 1: bias->out
// ---------------------------------------------------------------------------
#define TILE_B  16384
#define STAGE_B (4*TILE_B)
#define STAGES  3

__global__ __launch_bounds__(256, 1) void gemm_mma(
    const __nv_bfloat16* __restrict__ Ahi, const __nv_bfloat16* __restrict__ Alo,
    const __nv_bfloat16* __restrict__ Bhi, const __nv_bfloat16* __restrict__ Blo,
    int K, int mode,
    const float* __restrict__ bias,
    const float* __restrict__ cosb, const float* __restrict__ sinb,
    const float* __restrict__ logn,
    float* __restrict__ out, int Nout)
{
    extern __shared__ char smem[];
    const uint32_t sbase = smem_u32(smem);
    const int tid = threadIdx.x;
    const int wid = tid >> 5, lane = tid & 31;
    const int bm = blockIdx.y * 128, bn = blockIdx.x * 128;
    const int NCH = K >> 6;

    auto load_stage = [&](int ch, int buf) {
        const int k0 = ch << 6;
        const uint32_t stb = sbase + buf * STAGE_B;
#pragma unroll
        for (int i = 0; i < 16; i++) {
            int idx = i * 256 + tid;
            int mat = idx >> 10, local = idx & 1023;
            int row = local >> 3, seg = local & 7;
            const __nv_bfloat16* src;
            if (mat == 0)      src = Ahi + ((size_t)(bm + row) * K + k0 + seg * 8);
            else if (mat == 1) src = Alo + ((size_t)(bm + row) * K + k0 + seg * 8);
            else if (mat == 2) src = Bhi + ((size_t)(bn + row) * K + k0 + seg * 8);
            else               src = Blo + ((size_t)(bn + row) * K + k0 + seg * 8);
            cp16(stb + mat * TILE_B + swz(row * 128 + seg * 16), src);
        }
        asm volatile("cp.async.commit_group;" ::: "memory");
    };

    float acc[16][4];
#pragma unroll
    for (int f = 0; f < 16; f++)
#pragma unroll
        for (int j = 0; j < 4; j++) acc[f][j] = 0.f;

    // prologue: prefetch distance 2
    load_stage(0, 0);
    if (NCH > 1) load_stage(1, 1);
    else asm volatile("cp.async.commit_group;" ::: "memory");

    const int a_row = wid * 16 + (lane & 15);
    const int a_seg = (lane >> 4);
    const int b_row = (lane & 7) + ((lane >> 4) << 3);
    const int b_seg = (lane >> 3) & 1;

    for (int it = 0; it < NCH; it++) {
        asm volatile("cp.async.wait_group 1;" ::: "memory");   // chunk it landed
        __syncthreads();                                       // prev reads of buf (it+2)%3 done
        int nx = it + 2;
        if (nx < NCH) load_stage(nx, nx % STAGES);             // overlaps MMA below
        else asm volatile("cp.async.commit_group;" ::: "memory");

        const uint32_t stb = sbase + (it % STAGES) * STAGE_B;
        const uint32_t sAh = stb, sAl = stb + TILE_B;
        const uint32_t sBh = stb + 2 * TILE_B, sBl = stb + 3 * TILE_B;

#pragma unroll
        for (int ks = 0; ks < 4; ks++) {
            uint32_t ah[4], al[4], bh[32], bl[32];
            uint32_t aoff = swz((uint32_t)(a_row * 128 + (ks * 2 + a_seg) * 16));
            ldmx4(ah, sAh + aoff);
            ldmx4(al, sAl + aoff);
#pragma unroll
            for (int f2 = 0; f2 < 8; f2++) {
                uint32_t boff = swz((uint32_t)((f2 * 16 + b_row) * 128 + (ks * 2 + b_seg) * 16));
                ldmx4(bh + f2 * 4, sBh + boff);
                ldmx4(bl + f2 * 4, sBl + boff);
            }
#pragma unroll
            for (int f = 0; f < 16; f++) mma16816(acc[f], ah, bh + (f >> 1) * 4 + (f & 1) * 2);
#pragma unroll
            for (int f = 0; f < 16; f++) mma16816(acc[f], ah, bl + (f >> 1) * 4 + (f & 1) * 2);
#pragma unroll
            for (int f = 0; f < 16; f++) mma16816(acc[f], al, bh + (f >> 1) * 4 + (f & 1) * 2);
        }
    }

    // epilogue: row = bm + wid*16 + l/4 + (j>=2)*8, col = 8f + (l%4)*2 + (j&1)
    const int r_base = bm + wid * 16 + (lane >> 2);
    const int c_base = (lane & 3) * 2;

    if (mode == 0) {
        const int part = bn >> 12;
        const int head = (bn & 4095) >> 7;
        __nv_bfloat16* dhi = (part == 0) ? g_Qhi : (part == 1) ? g_Khi : g_Vhi;
        __nv_bfloat16* dlo = (part == 0) ? g_Qlo : (part == 1) ? g_Klo : g_Vlo;
#pragma unroll
        for (int rs = 0; rs < 2; rs++) {
            const int token = r_base + rs * 8;
            const int b_ = token >> 11, sPos = token & 2047;
            const size_t obase = (((size_t)(b_ * NH_ + head)) * S_ + sPos) * HD_;
            const float qs = logn[sPos] * 0.08838834764831845f;
            const float* crow = cosb + sPos * HD_;
            const float* srow = sinb + sPos * HD_;
#pragma unroll
            for (int f = 0; f < 8; f++) {
                const int d = f * 8 + c_base;          // 0..63
                float x0a = acc[f][rs * 2]     + bias[bn + d];
                float x0b = acc[f][rs * 2 + 1] + bias[bn + d + 1];
                float x1a = acc[f + 8][rs * 2]     + bias[bn + d + 64];
                float x1b = acc[f + 8][rs * 2 + 1] + bias[bn + d + 65];
                float y0a, y0b, y1a, y1b;
                if (part == 2) {
                    y0a = x0a; y0b = x0b; y1a = x1a; y1b = x1b;
                } else {
                    float2 c0 = *(const float2*)(crow + d);
                    float2 s0 = *(const float2*)(srow + d);
                    float2 c1 = *(const float2*)(crow + d + 64);
                    float2 s1 = *(const float2*)(srow + d + 64);
                    y0a = x0a * c0.x - x1a * s0.x;
                    y0b = x0b * c0.y - x1b * s0.y;
                    y1a = x1a * c1.x + x0a * s1.x;
                    y1b = x1b * c1.y + x0b * s1.y;
                    if (part == 0) { y0a *= qs; y0b *= qs; y1a *= qs; y1b *= qs; }
                }
                split_store(dhi, dlo, obase + d,      y0a, y0b);
                split_store(dhi, dlo, obase + d + 64, y1a, y1b);
            }
        }
    } else {
#pragma unroll
        for (int rs = 0; rs < 2; rs++) {
            const int token = r_base + rs * 8;
            float* orow = out + (size_t)token * Nout + bn;
#pragma unroll
            for (int f = 0; f < 16; f++) {
                const int c = f * 8 + c_base;
                float v0 = acc[f][rs * 2]     + bias[bn + c];
                float v1 = acc[f][rs * 2 + 1] + bias[bn + c + 1];
                *(float2*)(orow + c) = make_float2(v0, v1);
            }
        }
    }
}

// ---------------------------------------------------------------------------
// tensor-core causal flash attention, split-bf16 mma, fp32 softmax.
// BM=128 q-rows per CTA, BN=64 keys per iteration, 8 warps (16 q-rows each).
// smem: Qhi 32K | Qlo 32K | 2 stages of (Khi Klo Vhi Vlo, 16K each) = 192K.
// (unchanged from the R5 champion)
// ---------------------------------------------------------------------------
__global__ __launch_bounds__(256, 1) void attn_mma()
{
    extern __shared__ char smem[];
    const uint32_t sbase = smem_u32(smem);
    const uint32_t QHI = sbase, QLO = sbase + 32768;
    const int qt = blockIdx.x, bh = blockIdx.y;
    const int tid = threadIdx.x, wid = tid >> 5, lane = tid & 31;
    const int q0 = qt * 128;
    const size_t inb = (size_t)bh * S_ * HD_;
    const int ktiles = 2 * qt + 2;

#pragma unroll
    for (int i = 0; i < 16; i++) {
        int idx = i * 256 + tid;
        int m = idx >> 11, lidx = idx & 2047;
        int row = lidx >> 4, seg = lidx & 15;
        int half = seg >> 3, s8 = seg & 7;
        const __nv_bfloat16* src = (m ? g_Qlo : g_Qhi) + inb +
            (size_t)(q0 + row) * HD_ + half * 64 + s8 * 8;
        cp16((m ? QLO : QHI) + half * 16384 + swz(row * 128 + s8 * 16), src);
    }

    auto load_kv = [&](int kt, int buf) {
        const uint32_t stb = sbase + 65536 + buf * 65536;
        const int k0 = kt * 64;
#pragma unroll
        for (int i = 0; i < 16; i++) {
            int idx = i * 256 + tid;
            int m = idx >> 10, lidx = idx & 1023;
            int row = lidx >> 4, seg = lidx & 15;
            int half = seg >> 3, s8 = seg & 7;
            const __nv_bfloat16* src =
                ((m == 0) ? g_Khi : (m == 1) ? g_Klo : (m == 2) ? g_Vhi : g_Vlo) +
                inb + (size_t)(k0 + row) * HD_ + half * 64 + s8 * 8;
            cp16(stb + m * 16384 + half * 8192 + swz(row * 128 + s8 * 16), src);
        }
        asm volatile("cp.async.commit_group;" ::: "memory");
    };

    load_kv(0, 0);
    if (ktiles > 1) load_kv(1, 1);
    else asm volatile("cp.async.commit_group;" ::: "memory");

    asm volatile("cp.async.wait_group 1;" ::: "memory");
    __syncthreads();

    const int a_row = wid * 16 + (lane & 15);
    const int a_seg = lane >> 4;
    uint32_t qh[8][4], ql[8][4];
#pragma unroll
    for (int ks = 0; ks < 8; ks++) {
        uint32_t aoff = (ks >> 2) * 16384 + swz((uint32_t)(a_row * 128 + ((ks & 3) * 2 + a_seg) * 16));
        ldmx4(qh[ks], QHI + aoff);
        ldmx4(ql[ks], QLO + aoff);
    }

    const int b_row = (lane & 7) + ((lane >> 4) << 3);
    const int b_seg = (lane >> 3) & 1;
    const int r0g = q0 + wid * 16 + (lane >> 2);

    float of[16][4];
#pragma unroll
    for (int nf = 0; nf < 16; nf++)
#pragma unroll
        for (int j = 0; j < 4; j++) of[nf][j] = 0.f;
    float m0 = -1e30f, m1 = -1e30f, l0 = 0.f, l1 = 0.f;

    for (int kt = 0; kt < ktiles; kt++) {
        asm volatile("cp.async.wait_group 1;" ::: "memory");
        __syncthreads();
        const uint32_t stb = sbase + 65536 + (kt & 1) * 65536;
        const uint32_t KHI = stb, KLO = stb + 16384, VHI = stb + 32768, VLO = stb + 49152;
        const int k0 = kt * 64;

        float sacc[8][4];
#pragma unroll
        for (int n = 0; n < 8; n++)
#pragma unroll
            for (int j = 0; j < 4; j++) sacc[n][j] = 0.f;
#pragma unroll
        for (int ks = 0; ks < 8; ks++) {
            uint32_t bh16[16], bl16[16];
            uint32_t hoff = (ks >> 2) * 8192;
            uint32_t soff = ((ks & 3) * 2 + b_seg) * 16;
#pragma unroll
            for (int f2 = 0; f2 < 4; f2++) {
                uint32_t boff = hoff + swz((uint32_t)((f2 * 16 + b_row) * 128 + soff));
                ldmx4(bh16 + f2 * 4, KHI + boff);
                ldmx4(bl16 + f2 * 4, KLO + boff);
            }
#pragma unroll
            for (int n = 0; n < 8; n++) {
                const uint32_t* ph = bh16 + (n >> 1) * 4 + (n & 1) * 2;
                const uint32_t* pl = bl16 + (n >> 1) * 4 + (n & 1) * 2;
                mma16816(sacc[n], qh[ks], ph);
                mma16816(sacc[n], qh[ks], pl);
                mma16816(sacc[n], ql[ks], ph);
            }
        }

        if (kt >= 2 * qt) {
#pragma unroll
            for (int n = 0; n < 8; n++) {
#pragma unroll
                for (int j = 0; j < 4; j++) {
                    int key = k0 + n * 8 + (lane & 3) * 2 + (j & 1);
                    int row = r0g + ((j >> 1) << 3);
                    if (key > row) sacc[n][j] = -1e30f;
                }
            }
        }

        float mx0 = -1e30f, mx1 = -1e30f;
#pragma unroll
        for (int n = 0; n < 8; n++) {
            mx0 = fmaxf(mx0, fmaxf(sacc[n][0], sacc[n][1]));
            mx1 = fmaxf(mx1, fmaxf(sacc[n][2], sacc[n][3]));
        }
        mx0 = fmaxf(mx0, __shfl_xor_sync(0xffffffffu, mx0, 1));
        mx0 = fmaxf(mx0, __shfl_xor_sync(0xffffffffu, mx0, 2));
        mx1 = fmaxf(mx1, __shfl_xor_sync(0xffffffffu, mx1, 1));
        mx1 = fmaxf(mx1, __shfl_xor_sync(0xffffffffu, mx1, 2));
        float mn0 = fmaxf(m0, mx0), mn1 = fmaxf(m1, mx1);
        float al0 = __expf(m0 - mn0), al1 = __expf(m1 - mn1);
        m0 = mn0; m1 = mn1;
        float rs0 = 0.f, rs1 = 0.f;
#pragma unroll
        for (int n = 0; n < 8; n++) {
            sacc[n][0] = __expf(sacc[n][0] - mn0);
            sacc[n][1] = __expf(sacc[n][1] - mn0);
            sacc[n][2] = __expf(sacc[n][2] - mn1);
            sacc[n][3] = __expf(sacc[n][3] - mn1);
            rs0 += sacc[n][0] + sacc[n][1];
            rs1 += sacc[n][2] + sacc[n][3];
        }
        rs0 += __shfl_xor_sync(0xffffffffu, rs0, 1);
        rs0 += __shfl_xor_sync(0xffffffffu, rs0, 2);
        rs1 += __shfl_xor_sync(0xffffffffu, rs1, 1);
        rs1 += __shfl_xor_sync(0xffffffffu, rs1, 2);
        l0 = l0 * al0 + rs0;
        l1 = l1 * al1 + rs1;
#pragma unroll
        for (int nf = 0; nf < 16; nf++) {
            of[nf][0] *= al0; of[nf][1] *= al0;
            of[nf][2] *= al1; of[nf][3] *= al1;
        }

#pragma unroll
        for (int kc = 0; kc < 4; kc++) {
            uint32_t aph[4], apl[4];
            const int n0 = 2 * kc, n1 = 2 * kc + 1;
            float h00 = __bfloat162float(__float2bfloat16(sacc[n0][0]));
            float h01 = __bfloat162float(__float2bfloat16(sacc[n0][1]));
            float h02 = __bfloat162float(__float2bfloat16(sacc[n0][2]));
            float h03 = __bfloat162float(__float2bfloat16(sacc[n0][3]));
            float h10 = __bfloat162float(__float2bfloat16(sacc[n1][0]));
            float h11 = __bfloat162float(__float2bfloat16(sacc[n1][1]));
            float h12 = __bfloat162float(__float2bfloat16(sacc[n1][2]));
            float h13 = __bfloat162float(__float2bfloat16(sacc[n1][3]));
            aph[0] = pack_bf2(h00, h01); aph[1] = pack_bf2(h02, h03);
            aph[2] = pack_bf2(h10, h11); aph[3] = pack_bf2(h12, h13);
            apl[0] = pack_bf2(sacc[n0][0] - h00, sacc[n0][1] - h01);
            apl[1] = pack_bf2(sacc[n0][2] - h02, sacc[n0][3] - h03);
            apl[2] = pack_bf2(sacc[n1][0] - h10, sacc[n1][1] - h11);
            apl[3] = pack_bf2(sacc[n1][2] - h12, sacc[n1][3] - h13);
#pragma unroll
            for (int f = 0; f < 8; f++) {
                int s = 2 * f + (lane >> 4);
                uint32_t voff = (s >> 3) * 8192 +
                    swz((uint32_t)((kc * 16 + (lane & 15)) * 128 + (s & 7) * 16));
                uint32_t vh[4], vl[4];
                ldmx4t(vh, VHI + voff);
                ldmx4t(vl, VLO + voff);
                mma16816(of[2 * f],     aph, vh);
                mma16816(of[2 * f],     apl, vh);
                mma16816(of[2 * f],     aph, vl);
                mma16816(of[2 * f + 1], aph, vh + 2);
                mma16816(of[2 * f + 1], apl, vh + 2);
                mma16816(of[2 * f + 1], aph, vl + 2);
            }
        }

        __syncthreads();
        if (kt + 2 < ktiles) load_kv(kt + 2, kt & 1);
        else asm volatile("cp.async.commit_group;" ::: "memory");
    }

    const int b_ = bh >> 5, h = bh & 31;
    const float inv0 = 1.f / l0, inv1 = 1.f / l1;
    const int row0 = q0 + wid * 16 + (lane >> 2);
    const size_t ob0 = ((size_t)(b_ * S_ + row0)) * H_ + h * HD_;
    const size_t ob1 = ((size_t)(b_ * S_ + row0 + 8)) * H_ + h * HD_;
#pragma unroll
    for (int nf = 0; nf < 16; nf++) {
        int d = nf * 8 + (lane & 3) * 2;
        split_store(g_Chi, g_Clo, ob0 + d, of[nf][0] * inv0, of[nf][1] * inv0);
        split_store(g_Chi, g_Clo, ob1 + d, of[nf][2] * inv1, of[nf][3] * inv1);
    }
}

// ---------------------------------------------------------------------------
extern "C" void kernel_launch(void* const* d_in, const int* in_sizes, int n_in,
                              void* d_out, int out_size)
{
    const float* hidden = (const float*)d_in[0];
    const float* w_attn = (const float*)d_in[1];
    const float* b_attn = (const float*)d_in[2];
    const float* w_proj = (const float*)d_in[3];
    const float* b_proj = (const float*)d_in[4];
    const float* cosb   = (const float*)d_in[5];
    const float* sinb   = (const float*)d_in[6];
    const float* logn   = (const float*)d_in[7];
    float* out = (float*)d_out;

    __nv_bfloat16 *ahi, *alo, *whi, *wlo, *phi, *plo, *chi, *clo;
    cudaGetSymbolAddress((void**)&ahi, g_Ahi); cudaGetSymbolAddress((void**)&alo, g_Alo);
    cudaGetSymbolAddress((void**)&whi, g_Whi); cudaGetSymbolAddress((void**)&wlo, g_Wlo);
    cudaGetSymbolAddress((void**)&phi, g_Phi); cudaGetSymbolAddress((void**)&plo, g_Plo);
    cudaGetSymbolAddress((void**)&chi, g_Chi); cudaGetSymbolAddress((void**)&clo, g_Clo);

    // 1) split conversions
    {
        int n1 = T_ * H_;   f32_split<<<n1 / 1024, 256>>>(hidden, ahi, alo, n1);
        int n2 = N3_ * H_;  f32_split<<<n2 / 1024, 256>>>(w_attn, whi, wlo, n2);
        int n3 = H_ * H_;   f32_split<<<n3 / 1024, 256>>>(w_proj, phi, plo, n3);
    }

    const int gsmem = STAGES * STAGE_B;  // 196608
    cudaFuncSetAttribute(gemm_mma, cudaFuncAttributeMaxDynamicSharedMemorySize, gsmem);

    // 2) QKV GEMM fused bias+RoPE+logn, writes split-bf16 Q/K/V
    gemm_mma<<<dim3(N3_ / 128, T_ / 128), 256, gsmem>>>(
        ahi, alo, whi, wlo, H_, 0, b_attn, cosb, sinb, logn, nullptr, 0);

    // 3) tensor-core causal flash attention, writes split-bf16 ctx
    const int asmem = 65536 + 2 * 65536;  // 192KB
    cudaFuncSetAttribute(attn_mma, cudaFuncAttributeMaxDynamicSharedMemorySize, asmem);
    attn_mma<<<dim3(S_ / 128, B_ * NH_), 256, asmem>>>();

    // 4) output projection + bias
    gemm_mma<<<dim3(H_ / 128, T_ / 128), 256, gsmem>>>(
        chi, clo, phi, plo, H_, 1, b_proj, nullptr, nullptr, nullptr, out, H_);
}

// round 13
// speedup vs baseline: 1.3817x; 1.3817x over previous
#include <cuda_runtime.h>
#include <cuda_bf16.h>
#include <cuda_fp16.h>
#include <cstdint>
#include <math.h>

#define B_  2
#define S_  2048
#define H_  4096
#define NH_ 32
#define HD_ 128
#define T_  (B_*S_)    // 4096 tokens
#define N3_ (3*H_)     // 12288

// ---------------- scratch (__device__ globals; no allocation allowed) -------
__device__ __nv_bfloat16 g_Qhi[(size_t)B_*NH_*S_*HD_];  // [bh][s][d] bf16 split
__device__ __nv_bfloat16 g_Qlo[(size_t)B_*NH_*S_*HD_];
__device__ __nv_bfloat16 g_Khi[(size_t)B_*NH_*S_*HD_];
__device__ __nv_bfloat16 g_Klo[(size_t)B_*NH_*S_*HD_];
__device__ __nv_bfloat16 g_Vhi[(size_t)B_*NH_*S_*HD_];
__device__ __nv_bfloat16 g_Vlo[(size_t)B_*NH_*S_*HD_];

__device__ __half g_Ahi[(size_t)T_*H_];     // hidden fp16 split (exact pair)
__device__ __half g_Alo[(size_t)T_*H_];
__device__ __half g_Wh [(size_t)N3_*H_];    // w_attn fp16 (single field)
__device__ __half g_Ph [(size_t)H_*H_];     // w_proj fp16 (single field)
__device__ __half g_Chi[(size_t)T_*H_];     // ctx fp16 split (exact pair)
__device__ __half g_Clo[(size_t)T_*H_];

// ---------------- helpers ---------------------------------------------------
__device__ __forceinline__ uint32_t smem_u32(const void* p) {
    uint32_t a;
    asm("{ .reg .u64 t; cvta.to.shared.u64 t, %1; cvt.u32.u64 %0, t; }" : "=r"(a) : "l"(p));
    return a;
}
__device__ __forceinline__ uint32_t swz(uint32_t o) { return o ^ ((o >> 3) & 0x70); }

__device__ __forceinline__ void cp16(uint32_t dst, const void* src) {
    asm volatile("cp.async.cg.shared.global [%0], [%1], 16;" :: "r"(dst), "l"(src));
}
__device__ __forceinline__ void ldmx4(uint32_t* r, uint32_t addr) {
    asm volatile("ldmatrix.sync.aligned.m8n8.x4.shared.b16 {%0,%1,%2,%3}, [%4];"
        : "=r"(r[0]), "=r"(r[1]), "=r"(r[2]), "=r"(r[3]) : "r"(addr));
}
__device__ __forceinline__ void ldmx4t(uint32_t* r, uint32_t addr) {
    asm volatile("ldmatrix.sync.aligned.m8n8.x4.trans.shared.b16 {%0,%1,%2,%3}, [%4];"
        : "=r"(r[0]), "=r"(r[1]), "=r"(r[2]), "=r"(r[3]) : "r"(addr));
}
// bf16 mma (attention)
__device__ __forceinline__ void mma16816(float* c, const uint32_t* a, const uint32_t* b) {
    asm volatile("mma.sync.aligned.m16n8k16.row.col.f32.bf16.bf16.f32 "
        "{%0,%1,%2,%3}, {%4,%5,%6,%7}, {%8,%9}, {%0,%1,%2,%3};"
        : "+f"(c[0]), "+f"(c[1]), "+f"(c[2]), "+f"(c[3])
        : "r"(a[0]), "r"(a[1]), "r"(a[2]), "r"(a[3]), "r"(b[0]), "r"(b[1]));
}
// fp16 mma (weight GEMMs)
__device__ __forceinline__ void mma16816h(float* c, const uint32_t* a, const uint32_t* b) {
    asm volatile("mma.sync.aligned.m16n8k16.row.col.f32.f16.f16.f32 "
        "{%0,%1,%2,%3}, {%4,%5,%6,%7}, {%8,%9}, {%0,%1,%2,%3};"
        : "+f"(c[0]), "+f"(c[1]), "+f"(c[2]), "+f"(c[3])
        : "r"(a[0]), "r"(a[1]), "r"(a[2]), "r"(a[3]), "r"(b[0]), "r"(b[1]));
}
__device__ __forceinline__ uint32_t pack_bf2(float x, float y) {
    __nv_bfloat162 t = __floats2bfloat162_rn(x, y);
    return *(uint32_t*)&t;
}
__device__ __forceinline__ void split_store_bf(__nv_bfloat16* hi, __nv_bfloat16* lo,
                                               size_t off, float x, float y) {
    __nv_bfloat16 hx = __float2bfloat16(x), hy = __float2bfloat16(y);
    *(__nv_bfloat162*)(hi + off) = __nv_bfloat162(hx, hy);
    *(__nv_bfloat162*)(lo + off) = __nv_bfloat162(
        __float2bfloat16(x - __bfloat162float(hx)),
        __float2bfloat16(y - __bfloat162float(hy)));
}
__device__ __forceinline__ void split_store_h(__half* hi, __half* lo,
                                              size_t off, float x, float y) {
    __half hx = __float2half_rn(x), hy = __float2half_rn(y);
    *(__half2*)(hi + off) = __half2(hx, hy);
    *(__half2*)(lo + off) = __half2(
        __float2half_rn(x - __half2float(hx)),
        __float2half_rn(y - __half2float(hy)));
}

// ---------------------------------------------------------------------------
// fp32 -> fp16 (hi, lo) split     and     fp32 -> fp16 single
// ---------------------------------------------------------------------------
__global__ __launch_bounds__(256) void f32_split_h(
    const float* __restrict__ x, __half* __restrict__ hi,
    __half* __restrict__ lo, int n)
{
    int i = (blockIdx.x * 256 + threadIdx.x) * 4;
    if (i >= n) return;
    float4 v = *(const float4*)(x + i);
    split_store_h(hi, lo, i, v.x, v.y);
    split_store_h(hi, lo, i + 2, v.z, v.w);
}
__global__ __launch_bounds__(256) void f32_to_h(
    const float* __restrict__ x, __half* __restrict__ hi, int n)
{
    int i = (blockIdx.x * 256 + threadIdx.x) * 4;
    if (i >= n) return;
    float4 v = *(const float4*)(x + i);
    *(__half2*)(hi + i)     = __half2(__float2half_rn(v.x), __float2half_rn(v.y));
    *(__half2*)(hi + i + 2) = __half2(__float2half_rn(v.z), __float2half_rn(v.w));
}

// ---------------------------------------------------------------------------
// mma.sync fp16 2-term GEMM: C[M,N] = (Ahi+Alo)[M,K] @ Bh[N,K]^T
// BM=128, BN=128, BK=64, 3-stage cp.async, 256 threads / 8 warps
// (warp = 16m x 128n; champion R5 pipeline structure).
// mode 0: QKV epilogue (bias+RoPE+logn -> bf16-split Q/K/V)
// mode 1: proj epilogue (bias -> fp32 out)
// ---------------------------------------------------------------------------
#define TILE_B  16384
#define STAGE_B (3*TILE_B)          // Ahi, Alo, Bh
#define STAGES  3

__global__ __launch_bounds__(256, 1) void gemm_mma(
    const __half* __restrict__ Ahi, const __half* __restrict__ Alo,
    const __half* __restrict__ Bh,
    int K, int mode,
    const float* __restrict__ bias,
    const float* __restrict__ cosb, const float* __restrict__ sinb,
    const float* __restrict__ logn,
    float* __restrict__ out, int Nout)
{
    extern __shared__ char smem[];
    const uint32_t sbase = smem_u32(smem);
    const int tid = threadIdx.x;
    const int wid = tid >> 5, lane = tid & 31;
    const int bm = blockIdx.y * 128, bn = blockIdx.x * 128;
    const int NCH = K >> 6;

    auto load_stage = [&](int ch, int buf) {
        const int k0 = ch << 6;
        const uint32_t stb = sbase + buf * STAGE_B;
#pragma unroll
        for (int i = 0; i < 12; i++) {
            int idx = i * 256 + tid;
            int mat = idx >> 10, local = idx & 1023;
            int row = local >> 3, seg = local & 7;
            const __half* src;
            if (mat == 0)      src = Ahi + ((size_t)(bm + row) * K + k0 + seg * 8);
            else if (mat == 1) src = Alo + ((size_t)(bm + row) * K + k0 + seg * 8);
            else               src = Bh  + ((size_t)(bn + row) * K + k0 + seg * 8);
            cp16(stb + mat * TILE_B + swz(row * 128 + seg * 16), src);
        }
        asm volatile("cp.async.commit_group;" ::: "memory");
    };

    float acc[16][4];
#pragma unroll
    for (int f = 0; f < 16; f++)
#pragma unroll
        for (int j = 0; j < 4; j++) acc[f][j] = 0.f;

#pragma unroll
    for (int s = 0; s < STAGES; s++) {
        if (s < NCH) load_stage(s, s);
        else asm volatile("cp.async.commit_group;" ::: "memory");
    }

    const int a_row = wid * 16 + (lane & 15);
    const int a_seg = (lane >> 4);
    const int b_row = (lane & 7) + ((lane >> 4) << 3);
    const int b_seg = (lane >> 3) & 1;

    for (int it = 0; it < NCH; it++) {
        asm volatile("cp.async.wait_group %0;" :: "n"(STAGES - 1) : "memory");
        __syncthreads();
        const uint32_t stb = sbase + (it % STAGES) * STAGE_B;
        const uint32_t sAh = stb, sAl = stb + TILE_B, sBh = stb + 2 * TILE_B;

#pragma unroll
        for (int ks = 0; ks < 4; ks++) {
            uint32_t ah[4], al[4], bh[32];
            uint32_t aoff = swz((uint32_t)(a_row * 128 + (ks * 2 + a_seg) * 16));
            ldmx4(ah, sAh + aoff);
            ldmx4(al, sAl + aoff);
#pragma unroll
            for (int f2 = 0; f2 < 8; f2++) {
                uint32_t boff = swz((uint32_t)((f2 * 16 + b_row) * 128 + (ks * 2 + b_seg) * 16));
                ldmx4(bh + f2 * 4, sBh + boff);
            }
#pragma unroll
            for (int f = 0; f < 16; f++) mma16816h(acc[f], ah, bh + (f >> 1) * 4 + (f & 1) * 2);
#pragma unroll
            for (int f = 0; f < 16; f++) mma16816h(acc[f], al, bh + (f >> 1) * 4 + (f & 1) * 2);
        }
        __syncthreads();
        int nx = it + STAGES;
        if (nx < NCH) load_stage(nx, it % STAGES);
        else asm volatile("cp.async.commit_group;" ::: "memory");
    }

    // epilogue: row = bm + wid*16 + l/4 + (j>=2)*8, col = 8f + (l%4)*2 + (j&1)
    const int r_base = bm + wid * 16 + (lane >> 2);
    const int c_base = (lane & 3) * 2;

    if (mode == 0) {
        const int part = bn >> 12;
        const int head = (bn & 4095) >> 7;
        __nv_bfloat16* dhi = (part == 0) ? g_Qhi : (part == 1) ? g_Khi : g_Vhi;
        __nv_bfloat16* dlo = (part == 0) ? g_Qlo : (part == 1) ? g_Klo : g_Vlo;
#pragma unroll
        for (int rs = 0; rs < 2; rs++) {
            const int token = r_base + rs * 8;
            const int b_ = token >> 11, sPos = token & 2047;
            const size_t obase = (((size_t)(b_ * NH_ + head)) * S_ + sPos) * HD_;
            const float qs = logn[sPos] * 0.08838834764831845f;
            const float* crow = cosb + sPos * HD_;
            const float* srow = sinb + sPos * HD_;
#pragma unroll
            for (int f = 0; f < 8; f++) {
                const int d = f * 8 + c_base;          // 0..63
                float x0a = acc[f][rs * 2]     + bias[bn + d];
                float x0b = acc[f][rs * 2 + 1] + bias[bn + d + 1];
                float x1a = acc[f + 8][rs * 2]     + bias[bn + d + 64];
                float x1b = acc[f + 8][rs * 2 + 1] + bias[bn + d + 65];
                float y0a, y0b, y1a, y1b;
                if (part == 2) {
                    y0a = x0a; y0b = x0b; y1a = x1a; y1b = x1b;
                } else {
                    float2 c0 = *(const float2*)(crow + d);
                    float2 s0 = *(const float2*)(srow + d);
                    float2 c1 = *(const float2*)(crow + d + 64);
                    float2 s1 = *(const float2*)(srow + d + 64);
                    y0a = x0a * c0.x - x1a * s0.x;
                    y0b = x0b * c0.y - x1b * s0.y;
                    y1a = x1a * c1.x + x0a * s1.x;
                    y1b = x1b * c1.y + x0b * s1.y;
                    if (part == 0) { y0a *= qs; y0b *= qs; y1a *= qs; y1b *= qs; }
                }
                split_store_bf(dhi, dlo, obase + d,      y0a, y0b);
                split_store_bf(dhi, dlo, obase + d + 64, y1a, y1b);
            }
        }
    } else {
#pragma unroll
        for (int rs = 0; rs < 2; rs++) {
            const int token = r_base + rs * 8;
            float* orow = out + (size_t)token * Nout + bn;
#pragma unroll
            for (int f = 0; f < 16; f++) {
                const int c = f * 8 + c_base;
                float v0 = acc[f][rs * 2]     + bias[bn + c];
                float v1 = acc[f][rs * 2 + 1] + bias[bn + c + 1];
                *(float2*)(orow + c) = make_float2(v0, v1);
            }
        }
    }
}

// ---------------------------------------------------------------------------
// tensor-core causal flash attention, split-bf16 mma, fp32 softmax.
// (champion R5 kernel; epilogue now writes fp16-split ctx for proj GEMM)
// ---------------------------------------------------------------------------
__global__ __launch_bounds__(256, 1) void attn_mma()
{
    extern __shared__ char smem[];
    const uint32_t sbase = smem_u32(smem);
    const uint32_t QHI = sbase, QLO = sbase + 32768;
    const int qt = blockIdx.x, bh = blockIdx.y;
    const int tid = threadIdx.x, wid = tid >> 5, lane = tid & 31;
    const int q0 = qt * 128;
    const size_t inb = (size_t)bh * S_ * HD_;
    const int ktiles = 2 * qt + 2;

#pragma unroll
    for (int i = 0; i < 16; i++) {
        int idx = i * 256 + tid;
        int m = idx >> 11, lidx = idx & 2047;
        int row = lidx >> 4, seg = lidx & 15;
        int half = seg >> 3, s8 = seg & 7;
        const __nv_bfloat16* src = (m ? g_Qlo : g_Qhi) + inb +
            (size_t)(q0 + row) * HD_ + half * 64 + s8 * 8;
        cp16((m ? QLO : QHI) + half * 16384 + swz(row * 128 + s8 * 16), src);
    }

    auto load_kv = [&](int kt, int buf) {
        const uint32_t stb = sbase + 65536 + buf * 65536;
        const int k0 = kt * 64;
#pragma unroll
        for (int i = 0; i < 16; i++) {
            int idx = i * 256 + tid;
            int m = idx >> 10, lidx = idx & 1023;
            int row = lidx >> 4, seg = lidx & 15;
            int half = seg >> 3, s8 = seg & 7;
            const __nv_bfloat16* src =
                ((m == 0) ? g_Khi : (m == 1) ? g_Klo : (m == 2) ? g_Vhi : g_Vlo) +
                inb + (size_t)(k0 + row) * HD_ + half * 64 + s8 * 8;
            cp16(stb + m * 16384 + half * 8192 + swz(row * 128 + s8 * 16), src);
        }
        asm volatile("cp.async.commit_group;" ::: "memory");
    };

    load_kv(0, 0);
    if (ktiles > 1) load_kv(1, 1);
    else asm volatile("cp.async.commit_group;" ::: "memory");

    asm volatile("cp.async.wait_group 1;" ::: "memory");
    __syncthreads();

    const int a_row = wid * 16 + (lane & 15);
    const int a_seg = lane >> 4;
    uint32_t qh[8][4], ql[8][4];
#pragma unroll
    for (int ks = 0; ks < 8; ks++) {
        uint32_t aoff = (ks >> 2) * 16384 + swz((uint32_t)(a_row * 128 + ((ks & 3) * 2 + a_seg) * 16));
        ldmx4(qh[ks], QHI + aoff);
        ldmx4(ql[ks], QLO + aoff);
    }

    const int b_row = (lane & 7) + ((lane >> 4) << 3);
    const int b_seg = (lane >> 3) & 1;
    const int r0g = q0 + wid * 16 + (lane >> 2);

    float of[16][4];
#pragma unroll
    for (int nf = 0; nf < 16; nf++)
#pragma unroll
        for (int j = 0; j < 4; j++) of[nf][j] = 0.f;
    float m0 = -1e30f, m1 = -1e30f, l0 = 0.f, l1 = 0.f;

    for (int kt = 0; kt < ktiles; kt++) {
        asm volatile("cp.async.wait_group 1;" ::: "memory");
        __syncthreads();
        const uint32_t stb = sbase + 65536 + (kt & 1) * 65536;
        const uint32_t KHI = stb, KLO = stb + 16384, VHI = stb + 32768, VLO = stb + 49152;
        const int k0 = kt * 64;

        float sacc[8][4];
#pragma unroll
        for (int n = 0; n < 8; n++)
#pragma unroll
            for (int j = 0; j < 4; j++) sacc[n][j] = 0.f;
#pragma unroll
        for (int ks = 0; ks < 8; ks++) {
            uint32_t bh16[16], bl16[16];
            uint32_t hoff = (ks >> 2) * 8192;
            uint32_t soff = ((ks & 3) * 2 + b_seg) * 16;
#pragma unroll
            for (int f2 = 0; f2 < 4; f2++) {
                uint32_t boff = hoff + swz((uint32_t)((f2 * 16 + b_row) * 128 + soff));
                ldmx4(bh16 + f2 * 4, KHI + boff);
                ldmx4(bl16 + f2 * 4, KLO + boff);
            }
#pragma unroll
            for (int n = 0; n < 8; n++) {
                const uint32_t* ph = bh16 + (n >> 1) * 4 + (n & 1) * 2;
                const uint32_t* pl = bl16 + (n >> 1) * 4 + (n & 1) * 2;
                mma16816(sacc[n], qh[ks], ph);
                mma16816(sacc[n], qh[ks], pl);
                mma16816(sacc[n], ql[ks], ph);
            }
        }

        if (kt >= 2 * qt) {
#pragma unroll
            for (int n = 0; n < 8; n++) {
#pragma unroll
                for (int j = 0; j < 4; j++) {
                    int key = k0 + n * 8 + (lane & 3) * 2 + (j & 1);
                    int row = r0g + ((j >> 1) << 3);
                    if (key > row) sacc[n][j] = -1e30f;
                }
            }
        }

        float mx0 = -1e30f, mx1 = -1e30f;
#pragma unroll
        for (int n = 0; n < 8; n++) {
            mx0 = fmaxf(mx0, fmaxf(sacc[n][0], sacc[n][1]));
            mx1 = fmaxf(mx1, fmaxf(sacc[n][2], sacc[n][3]));
        }
        mx0 = fmaxf(mx0, __shfl_xor_sync(0xffffffffu, mx0, 1));
        mx0 = fmaxf(mx0, __shfl_xor_sync(0xffffffffu, mx0, 2));
        mx1 = fmaxf(mx1, __shfl_xor_sync(0xffffffffu, mx1, 1));
        mx1 = fmaxf(mx1, __shfl_xor_sync(0xffffffffu, mx1, 2));
        float mn0 = fmaxf(m0, mx0), mn1 = fmaxf(m1, mx1);
        float al0 = __expf(m0 - mn0), al1 = __expf(m1 - mn1);
        m0 = mn0; m1 = mn1;
        float rs0 = 0.f, rs1 = 0.f;
#pragma unroll
        for (int n = 0; n < 8; n++) {
            sacc[n][0] = __expf(sacc[n][0] - mn0);
            sacc[n][1] = __expf(sacc[n][1] - mn0);
            sacc[n][2] = __expf(sacc[n][2] - mn1);
            sacc[n][3] = __expf(sacc[n][3] - mn1);
            rs0 += sacc[n][0] + sacc[n][1];
            rs1 += sacc[n][2] + sacc[n][3];
        }
        rs0 += __shfl_xor_sync(0xffffffffu, rs0, 1);
        rs0 += __shfl_xor_sync(0xffffffffu, rs0, 2);
        rs1 += __shfl_xor_sync(0xffffffffu, rs1, 1);
        rs1 += __shfl_xor_sync(0xffffffffu, rs1, 2);
        l0 = l0 * al0 + rs0;
        l1 = l1 * al1 + rs1;
#pragma unroll
        for (int nf = 0; nf < 16; nf++) {
            of[nf][0] *= al0; of[nf][1] *= al0;
            of[nf][2] *= al1; of[nf][3] *= al1;
        }

#pragma unroll
        for (int kc = 0; kc < 4; kc++) {
            uint32_t aph[4], apl[4];
            const int n0 = 2 * kc, n1 = 2 * kc + 1;
            float h00 = __bfloat162float(__float2bfloat16(sacc[n0][0]));
            float h01 = __bfloat162float(__float2bfloat16(sacc[n0][1]));
            float h02 = __bfloat162float(__float2bfloat16(sacc[n0][2]));
            float h03 = __bfloat162float(__float2bfloat16(sacc[n0][3]));
            float h10 = __bfloat162float(__float2bfloat16(sacc[n1][0]));
            float h11 = __bfloat162float(__float2bfloat16(sacc[n1][1]));
            float h12 = __bfloat162float(__float2bfloat16(sacc[n1][2]));
            float h13 = __bfloat162float(__float2bfloat16(sacc[n1][3]));
            aph[0] = pack_bf2(h00, h01); aph[1] = pack_bf2(h02, h03);
            aph[2] = pack_bf2(h10, h11); aph[3] = pack_bf2(h12, h13);
            apl[0] = pack_bf2(sacc[n0][0] - h00, sacc[n0][1] - h01);
            apl[1] = pack_bf2(sacc[n0][2] - h02, sacc[n0][3] - h03);
            apl[2] = pack_bf2(sacc[n1][0] - h10, sacc[n1][1] - h11);
            apl[3] = pack_bf2(sacc[n1][2] - h12, sacc[n1][3] - h13);
#pragma unroll
            for (int f = 0; f < 8; f++) {
                int s = 2 * f + (lane >> 4);
                uint32_t voff = (s >> 3) * 8192 +
                    swz((uint32_t)((kc * 16 + (lane & 15)) * 128 + (s & 7) * 16));
                uint32_t vh[4], vl[4];
                ldmx4t(vh, VHI + voff);
                ldmx4t(vl, VLO + voff);
                mma16816(of[2 * f],     aph, vh);
                mma16816(of[2 * f],     apl, vh);
                mma16816(of[2 * f],     aph, vl);
                mma16816(of[2 * f + 1], aph, vh + 2);
                mma16816(of[2 * f + 1], apl, vh + 2);
                mma16816(of[2 * f + 1], aph, vl + 2);
            }
        }

        __syncthreads();
        if (kt + 2 < ktiles) load_kv(kt + 2, kt & 1);
        else asm volatile("cp.async.commit_group;" ::: "memory");
    }

    // epilogue: ctx -> fp16 split (exact pair), token-major [t][h*HD+d]
    const int b_ = bh >> 5, h = bh & 31;
    const float inv0 = 1.f / l0, inv1 = 1.f / l1;
    const int row0 = q0 + wid * 16 + (lane >> 2);
    const size_t ob0 = ((size_t)(b_ * S_ + row0)) * H_ + h * HD_;
    const size_t ob1 = ((size_t)(b_ * S_ + row0 + 8)) * H_ + h * HD_;
#pragma unroll
    for (int nf = 0; nf < 16; nf++) {
        int d = nf * 8 + (lane & 3) * 2;
        split_store_h(g_Chi, g_Clo, ob0 + d, of[nf][0] * inv0, of[nf][1] * inv0);
        split_store_h(g_Chi, g_Clo, ob1 + d, of[nf][2] * inv1, of[nf][3] * inv1);
    }
}

// ---------------------------------------------------------------------------
extern "C" void kernel_launch(void* const* d_in, const int* in_sizes, int n_in,
                              void* d_out, int out_size)
{
    const float* hidden = (const float*)d_in[0];
    const float* w_attn = (const float*)d_in[1];
    const float* b_attn = (const float*)d_in[2];
    const float* w_proj = (const float*)d_in[3];
    const float* b_proj = (const float*)d_in[4];
    const float* cosb   = (const float*)d_in[5];
    const float* sinb   = (const float*)d_in[6];
    const float* logn   = (const float*)d_in[7];
    float* out = (float*)d_out;

    __half *ahi, *alo, *wh, *ph, *chi, *clo;
    cudaGetSymbolAddress((void**)&ahi, g_Ahi); cudaGetSymbolAddress((void**)&alo, g_Alo);
    cudaGetSymbolAddress((void**)&wh,  g_Wh);  cudaGetSymbolAddress((void**)&ph,  g_Ph);
    cudaGetSymbolAddress((void**)&chi, g_Chi); cudaGetSymbolAddress((void**)&clo, g_Clo);

    // 1) conversions: hidden -> fp16 hi/lo; weights -> fp16 single
    {
        int n1 = T_ * H_;   f32_split_h<<<n1 / 1024, 256>>>(hidden, ahi, alo, n1);
        int n2 = N3_ * H_;  f32_to_h<<<n2 / 1024, 256>>>(w_attn, wh, n2);
        int n3 = H_ * H_;   f32_to_h<<<n3 / 1024, 256>>>(w_proj, ph, n3);
    }

    const int gsmem = STAGES * STAGE_B;  // 147456
    cudaFuncSetAttribute(gemm_mma, cudaFuncAttributeMaxDynamicSharedMemorySize, gsmem);

    // 2) QKV GEMM (fp16 2-term) fused bias+RoPE+logn, writes bf16-split Q/K/V
    gemm_mma<<<dim3(N3_ / 128, T_ / 128), 256, gsmem>>>(
        ahi, alo, wh, H_, 0, b_attn, cosb, sinb, logn, nullptr, 0);

    // 3) tensor-core causal flash attention (bf16 3-term), writes fp16-split ctx
    const int asmem = 65536 + 2 * 65536;  // 192KB
    cudaFuncSetAttribute(attn_mma, cudaFuncAttributeMaxDynamicSharedMemorySize, asmem);
    attn_mma<<<dim3(S_ / 128, B_ * NH_), 256, asmem>>>();

    // 4) output projection (fp16 2-term) + bias
    gemm_mma<<<dim3(H_ / 128, T_ / 128), 256, gsmem>>>(
        chi, clo, ph, H_, 1, b_proj, nullptr, nullptr, nullptr, out, H_);
}

// round 17
// speedup vs baseline: 1.5541x; 1.1248x over previous
#include <cuda_runtime.h>
#include <cuda_bf16.h>
#include <cuda_fp16.h>
#include <cstdint>
#include <math.h>

#define B_  2
#define S_  2048
#define H_  4096
#define NH_ 32
#define HD_ 128
#define T_  (B_*S_)    // 4096 tokens
#define N3_ (3*H_)     // 12288

// ---------------- scratch (__device__ globals; no allocation allowed) -------
__device__ __nv_bfloat16 g_Qhi[(size_t)B_*NH_*S_*HD_];  // [bh][s][d] bf16 split
__device__ __nv_bfloat16 g_Qlo[(size_t)B_*NH_*S_*HD_];
__device__ __nv_bfloat16 g_Khi[(size_t)B_*NH_*S_*HD_];
__device__ __nv_bfloat16 g_Klo[(size_t)B_*NH_*S_*HD_];
__device__ __nv_bfloat16 g_Vhi[(size_t)B_*NH_*S_*HD_];
__device__ __nv_bfloat16 g_Vlo[(size_t)B_*NH_*S_*HD_];

__device__ __half g_Ahi[(size_t)T_*H_];     // hidden fp16 split (exact pair)
__device__ __half g_Alo[(size_t)T_*H_];
__device__ __half g_Wh [(size_t)N3_*H_];    // w_attn fp16 (single field)
__device__ __half g_Ph [(size_t)H_*H_];     // w_proj fp16 (single field)
__device__ __half g_Chi[(size_t)T_*H_];     // ctx fp16 split (exact pair)
__device__ __half g_Clo[(size_t)T_*H_];

// ---------------- helpers ---------------------------------------------------
__device__ __forceinline__ uint32_t smem_u32(const void* p) {
    uint32_t a;
    asm("{ .reg .u64 t; cvta.to.shared.u64 t, %1; cvt.u32.u64 %0, t; }" : "=r"(a) : "l"(p));
    return a;
}
__device__ __forceinline__ uint32_t swz(uint32_t o) { return o ^ ((o >> 3) & 0x70); }

__device__ __forceinline__ void cp16(uint32_t dst, const void* src) {
    asm volatile("cp.async.cg.shared.global [%0], [%1], 16;" :: "r"(dst), "l"(src));
}
__device__ __forceinline__ void ldmx4(uint32_t* r, uint32_t addr) {
    asm volatile("ldmatrix.sync.aligned.m8n8.x4.shared.b16 {%0,%1,%2,%3}, [%4];"
        : "=r"(r[0]), "=r"(r[1]), "=r"(r[2]), "=r"(r[3]) : "r"(addr));
}
__device__ __forceinline__ void ldmx4t(uint32_t* r, uint32_t addr) {
    asm volatile("ldmatrix.sync.aligned.m8n8.x4.trans.shared.b16 {%0,%1,%2,%3}, [%4];"
        : "=r"(r[0]), "=r"(r[1]), "=r"(r[2]), "=r"(r[3]) : "r"(addr));
}
// bf16 mma (attention)
__device__ __forceinline__ void mma16816(float* c, const uint32_t* a, const uint32_t* b) {
    asm volatile("mma.sync.aligned.m16n8k16.row.col.f32.bf16.bf16.f32 "
        "{%0,%1,%2,%3}, {%4,%5,%6,%7}, {%8,%9}, {%0,%1,%2,%3};"
        : "+f"(c[0]), "+f"(c[1]), "+f"(c[2]), "+f"(c[3])
        : "r"(a[0]), "r"(a[1]), "r"(a[2]), "r"(a[3]), "r"(b[0]), "r"(b[1]));
}
// fp16 mma (weight GEMMs)
__device__ __forceinline__ void mma16816h(float* c, const uint32_t* a, const uint32_t* b) {
    asm volatile("mma.sync.aligned.m16n8k16.row.col.f32.f16.f16.f32 "
        "{%0,%1,%2,%3}, {%4,%5,%6,%7}, {%8,%9}, {%0,%1,%2,%3};"
        : "+f"(c[0]), "+f"(c[1]), "+f"(c[2]), "+f"(c[3])
        : "r"(a[0]), "r"(a[1]), "r"(a[2]), "r"(a[3]), "r"(b[0]), "r"(b[1]));
}
__device__ __forceinline__ uint32_t pack_bf2(float x, float y) {
    __nv_bfloat162 t = __floats2bfloat162_rn(x, y);
    return *(uint32_t*)&t;
}
__device__ __forceinline__ void split_store_bf(__nv_bfloat16* hi, __nv_bfloat16* lo,
                                               size_t off, float x, float y) {
    __nv_bfloat16 hx = __float2bfloat16(x), hy = __float2bfloat16(y);
    *(__nv_bfloat162*)(hi + off) = __nv_bfloat162(hx, hy);
    *(__nv_bfloat162*)(lo + off) = __nv_bfloat162(
        __float2bfloat16(x - __bfloat162float(hx)),
        __float2bfloat16(y - __bfloat162float(hy)));
}
__device__ __forceinline__ void split_store_h(__half* hi, __half* lo,
                                              size_t off, float x, float y) {
    __half hx = __float2half_rn(x), hy = __float2half_rn(y);
    *(__half2*)(hi + off) = __half2(hx, hy);
    *(__half2*)(lo + off) = __half2(
        __float2half_rn(x - __half2float(hx)),
        __float2half_rn(y - __half2float(hy)));
}

// ---------------------------------------------------------------------------
// fp32 -> fp16 (hi, lo) split     and     fp32 -> fp16 single
// ---------------------------------------------------------------------------
__global__ __launch_bounds__(256) void f32_split_h(
    const float* __restrict__ x, __half* __restrict__ hi,
    __half* __restrict__ lo, int n)
{
    int i = (blockIdx.x * 256 + threadIdx.x) * 4;
    if (i >= n) return;
    float4 v = *(const float4*)(x + i);
    split_store_h(hi, lo, i, v.x, v.y);
    split_store_h(hi, lo, i + 2, v.z, v.w);
}
__global__ __launch_bounds__(256) void f32_to_h(
    const float* __restrict__ x, __half* __restrict__ hi, int n)
{
    int i = (blockIdx.x * 256 + threadIdx.x) * 4;
    if (i >= n) return;
    float4 v = *(const float4*)(x + i);
    *(__half2*)(hi + i)     = __half2(__float2half_rn(v.x), __float2half_rn(v.y));
    *(__half2*)(hi + i + 2) = __half2(__float2half_rn(v.z), __float2half_rn(v.w));
}

// ---------------------------------------------------------------------------
// mma.sync fp16 2-term GEMM: C[M,N] = (Ahi+Alo)[M,K] @ Bh[N,K]^T
// BM=64, BN=128, BK=64, 3-stage cp.async, 256 threads / 8 warps,
// 2 CTAs per SM (32KB/stage -> 96KB smem; __launch_bounds__(256,2) caps regs).
// Warp (wm=wid>>1, wn=wid&1): rows [bm+16wm, +16),
// cols {bn + 16f + 8wn + 0..7 : f=0..7}  (RoPE pair = frags f, f+4).
// B frags: ldmatrix.x4 spanning 2 n8-groups via per-lane tile addressing.
// mode 0: QKV epilogue (bias+RoPE+logn -> bf16-split Q/K/V), mode 1: bias->out
// ---------------------------------------------------------------------------
#define STAGE_B 32768               // Ahi 8K | Alo 8K | B 16K
#define STAGES  3

__global__ __launch_bounds__(256, 2) void gemm_mma(
    const __half* __restrict__ Ahi, const __half* __restrict__ Alo,
    const __half* __restrict__ Bh,
    int K, int mode,
    const float* __restrict__ bias,
    const float* __restrict__ cosb, const float* __restrict__ sinb,
    const float* __restrict__ logn,
    float* __restrict__ out, int Nout)
{
    extern __shared__ char smem[];
    const uint32_t sbase = smem_u32(smem);
    const int tid = threadIdx.x;
    const int wid = tid >> 5, lane = tid & 31;
    const int wm = wid >> 1, wn = wid & 1;
    const int bm = blockIdx.y * 64, bn = blockIdx.x * 128;
    const int NCH = K >> 6;

    auto load_stage = [&](int ch, int buf) {
        const int k0 = ch << 6;
        const uint32_t stb = sbase + buf * STAGE_B;
#pragma unroll
        for (int i = 0; i < 8; i++) {
            int idx = i * 256 + tid;
            if (idx < 1024) {
                int arr = idx >> 9, local = idx & 511;
                int row = local >> 3, seg = local & 7;
                const __half* src = (arr ? Alo : Ahi) +
                    ((size_t)(bm + row) * K + k0 + seg * 8);
                cp16(stb + arr * 8192 + swz(row * 128 + seg * 16), src);
            } else {
                int local = idx - 1024;
                int row = local >> 3, seg = local & 7;
                const __half* src = Bh + ((size_t)(bn + row) * K + k0 + seg * 8);
                cp16(stb + 16384 + swz(row * 128 + seg * 16), src);
            }
        }
        asm volatile("cp.async.commit_group;" ::: "memory");
    };

    float acc[8][4];
#pragma unroll
    for (int f = 0; f < 8; f++)
#pragma unroll
        for (int j = 0; j < 4; j++) acc[f][j] = 0.f;

#pragma unroll
    for (int s = 0; s < STAGES; s++) {
        if (s < NCH) load_stage(s, s);
        else asm volatile("cp.async.commit_group;" ::: "memory");
    }

    // A: row = wm*16 + (lane&15), k-seg = ks*2 + (lane>>4)
    const int a_row = wm * 16 + (lane & 15);
    const int a_seg = lane >> 4;
    // B x4 over 2 n8-groups (verified in R9): per t, rows (2t+gsel)*16 + 8wn + (lane&7)
    const int b_row = 8 * wn + (lane & 7);
    const int b_gsel = (lane >> 4) & 1;
    const int b_seg = (lane >> 3) & 1;

    for (int it = 0; it < NCH; it++) {
        asm volatile("cp.async.wait_group %0;" :: "n"(STAGES - 1) : "memory");
        __syncthreads();
        const uint32_t stb = sbase + (it % STAGES) * STAGE_B;
        const uint32_t sAh = stb, sAl = stb + 8192, sB = stb + 16384;

#pragma unroll
        for (int ks = 0; ks < 4; ks++) {
            uint32_t ah[4], al[4], bh[16];
            uint32_t aoff = swz((uint32_t)(a_row * 128 + (ks * 2 + a_seg) * 16));
            ldmx4(ah, sAh + aoff);
            ldmx4(al, sAl + aoff);
#pragma unroll
            for (int t = 0; t < 4; t++) {
                int row = (2 * t + b_gsel) * 16 + b_row;
                uint32_t boff = swz((uint32_t)(row * 128 + (ks * 2 + b_seg) * 16));
                ldmx4(bh + 4 * t, sB + boff);
            }
#pragma unroll
            for (int f = 0; f < 8; f++) mma16816h(acc[f], ah, bh + 2 * f);
#pragma unroll
            for (int f = 0; f < 8; f++) mma16816h(acc[f], al, bh + 2 * f);
        }
        __syncthreads();
        int nx = it + STAGES;
        if (nx < NCH) load_stage(nx, it % STAGES);
        else asm volatile("cp.async.commit_group;" ::: "memory");
    }

    // epilogue: row = bm + 16wm + (l>>2) + 8*(j>=2), col = 16f + 8wn + (l&3)*2 + (j&1)
    const int r_base = bm + wm * 16 + (lane >> 2);
    const int c_off = wn * 8 + (lane & 3) * 2;

    if (mode == 0) {
        const int part = bn >> 12;
        const int head = (bn & 4095) >> 7;
        __nv_bfloat16* dhi = (part == 0) ? g_Qhi : (part == 1) ? g_Khi : g_Vhi;
        __nv_bfloat16* dlo = (part == 0) ? g_Qlo : (part == 1) ? g_Klo : g_Vlo;
#pragma unroll
        for (int rs = 0; rs < 2; rs++) {
            const int token = r_base + rs * 8;
            const int b_ = token >> 11, sPos = token & 2047;
            const size_t obase = (((size_t)(b_ * NH_ + head)) * S_ + sPos) * HD_;
            const float qs = logn[sPos] * 0.08838834764831845f;
            const float* crow = cosb + sPos * HD_;
            const float* srow = sinb + sPos * HD_;
#pragma unroll
            for (int f = 0; f < 4; f++) {
                const int d = f * 16 + c_off;          // 0..63
                float x0a = acc[f][rs * 2]     + bias[bn + d];
                float x0b = acc[f][rs * 2 + 1] + bias[bn + d + 1];
                float x1a = acc[f + 4][rs * 2]     + bias[bn + d + 64];
                float x1b = acc[f + 4][rs * 2 + 1] + bias[bn + d + 65];
                float y0a, y0b, y1a, y1b;
                if (part == 2) {
                    y0a = x0a; y0b = x0b; y1a = x1a; y1b = x1b;
                } else {
                    float2 c0 = *(const float2*)(crow + d);
                    float2 s0 = *(const float2*)(srow + d);
                    float2 c1 = *(const float2*)(crow + d + 64);
                    float2 s1 = *(const float2*)(srow + d + 64);
                    y0a = x0a * c0.x - x1a * s0.x;
                    y0b = x0b * c0.y - x1b * s0.y;
                    y1a = x1a * c1.x + x0a * s1.x;
                    y1b = x1b * c1.y + x0b * s1.y;
                    if (part == 0) { y0a *= qs; y0b *= qs; y1a *= qs; y1b *= qs; }
                }
                split_store_bf(dhi, dlo, obase + d,      y0a, y0b);
                split_store_bf(dhi, dlo, obase + d + 64, y1a, y1b);
            }
        }
    } else {
#pragma unroll
        for (int rs = 0; rs < 2; rs++) {
            const int token = r_base + rs * 8;
            float* orow = out + (size_t)token * Nout + bn;
#pragma unroll
            for (int f = 0; f < 8; f++) {
                const int c = f * 16 + c_off;
                float v0 = acc[f][rs * 2]     + bias[bn + c];
                float v1 = acc[f][rs * 2 + 1] + bias[bn + c + 1];
                *(float2*)(orow + c) = make_float2(v0, v1);
            }
        }
    }
}

// ---------------------------------------------------------------------------
// tensor-core causal flash attention, split-bf16 mma, fp32 softmax.
// (unchanged champion kernel; writes fp16-split ctx)
// ---------------------------------------------------------------------------
__global__ __launch_bounds__(256, 1) void attn_mma()
{
    extern __shared__ char smem[];
    const uint32_t sbase = smem_u32(smem);
    const uint32_t QHI = sbase, QLO = sbase + 32768;
    const int qt = blockIdx.x, bh = blockIdx.y;
    const int tid = threadIdx.x, wid = tid >> 5, lane = tid & 31;
    const int q0 = qt * 128;
    const size_t inb = (size_t)bh * S_ * HD_;
    const int ktiles = 2 * qt + 2;

#pragma unroll
    for (int i = 0; i < 16; i++) {
        int idx = i * 256 + tid;
        int m = idx >> 11, lidx = idx & 2047;
        int row = lidx >> 4, seg = lidx & 15;
        int half = seg >> 3, s8 = seg & 7;
        const __nv_bfloat16* src = (m ? g_Qlo : g_Qhi) + inb +
            (size_t)(q0 + row) * HD_ + half * 64 + s8 * 8;
        cp16((m ? QLO : QHI) + half * 16384 + swz(row * 128 + s8 * 16), src);
    }

    auto load_kv = [&](int kt, int buf) {
        const uint32_t stb = sbase + 65536 + buf * 65536;
        const int k0 = kt * 64;
#pragma unroll
        for (int i = 0; i < 16; i++) {
            int idx = i * 256 + tid;
            int m = idx >> 10, lidx = idx & 1023;
            int row = lidx >> 4, seg = lidx & 15;
            int half = seg >> 3, s8 = seg & 7;
            const __nv_bfloat16* src =
                ((m == 0) ? g_Khi : (m == 1) ? g_Klo : (m == 2) ? g_Vhi : g_Vlo) +
                inb + (size_t)(k0 + row) * HD_ + half * 64 + s8 * 8;
            cp16(stb + m * 16384 + half * 8192 + swz(row * 128 + s8 * 16), src);
        }
        asm volatile("cp.async.commit_group;" ::: "memory");
    };

    load_kv(0, 0);
    if (ktiles > 1) load_kv(1, 1);
    else asm volatile("cp.async.commit_group;" ::: "memory");

    asm volatile("cp.async.wait_group 1;" ::: "memory");
    __syncthreads();

    const int a_row = wid * 16 + (lane & 15);
    const int a_seg = lane >> 4;
    uint32_t qh[8][4], ql[8][4];
#pragma unroll
    for (int ks = 0; ks < 8; ks++) {
        uint32_t aoff = (ks >> 2) * 16384 + swz((uint32_t)(a_row * 128 + ((ks & 3) * 2 + a_seg) * 16));
        ldmx4(qh[ks], QHI + aoff);
        ldmx4(ql[ks], QLO + aoff);
    }

    const int b_row = (lane & 7) + ((lane >> 4) << 3);
    const int b_seg = (lane >> 3) & 1;
    const int r0g = q0 + wid * 16 + (lane >> 2);

    float of[16][4];
#pragma unroll
    for (int nf = 0; nf < 16; nf++)
#pragma unroll
        for (int j = 0; j < 4; j++) of[nf][j] = 0.f;
    float m0 = -1e30f, m1 = -1e30f, l0 = 0.f, l1 = 0.f;

    for (int kt = 0; kt < ktiles; kt++) {
        asm volatile("cp.async.wait_group 1;" ::: "memory");
        __syncthreads();
        const uint32_t stb = sbase + 65536 + (kt & 1) * 65536;
        const uint32_t KHI = stb, KLO = stb + 16384, VHI = stb + 32768, VLO = stb + 49152;
        const int k0 = kt * 64;

        float sacc[8][4];
#pragma unroll
        for (int n = 0; n < 8; n++)
#pragma unroll
            for (int j = 0; j < 4; j++) sacc[n][j] = 0.f;
#pragma unroll
        for (int ks = 0; ks < 8; ks++) {
            uint32_t bh16[16], bl16[16];
            uint32_t hoff = (ks >> 2) * 8192;
            uint32_t soff = ((ks & 3) * 2 + b_seg) * 16;
#pragma unroll
            for (int f2 = 0; f2 < 4; f2++) {
                uint32_t boff = hoff + swz((uint32_t)((f2 * 16 + b_row) * 128 + soff));
                ldmx4(bh16 + f2 * 4, KHI + boff);
                ldmx4(bl16 + f2 * 4, KLO + boff);
            }
#pragma unroll
            for (int n = 0; n < 8; n++) {
                const uint32_t* ph = bh16 + (n >> 1) * 4 + (n & 1) * 2;
                const uint32_t* pl = bl16 + (n >> 1) * 4 + (n & 1) * 2;
                mma16816(sacc[n], qh[ks], ph);
                mma16816(sacc[n], qh[ks], pl);
                mma16816(sacc[n], ql[ks], ph);
            }
        }

        if (kt >= 2 * qt) {
#pragma unroll
            for (int n = 0; n < 8; n++) {
#pragma unroll
                for (int j = 0; j < 4; j++) {
                    int key = k0 + n * 8 + (lane & 3) * 2 + (j & 1);
                    int row = r0g + ((j >> 1) << 3);
                    if (key > row) sacc[n][j] = -1e30f;
                }
            }
        }

        float mx0 = -1e30f, mx1 = -1e30f;
#pragma unroll
        for (int n = 0; n < 8; n++) {
            mx0 = fmaxf(mx0, fmaxf(sacc[n][0], sacc[n][1]));
            mx1 = fmaxf(mx1, fmaxf(sacc[n][2], sacc[n][3]));
        }
        mx0 = fmaxf(mx0, __shfl_xor_sync(0xffffffffu, mx0, 1));
        mx0 = fmaxf(mx0, __shfl_xor_sync(0xffffffffu, mx0, 2));
        mx1 = fmaxf(mx1, __shfl_xor_sync(0xffffffffu, mx1, 1));
        mx1 = fmaxf(mx1, __shfl_xor_sync(0xffffffffu, mx1, 2));
        float mn0 = fmaxf(m0, mx0), mn1 = fmaxf(m1, mx1);
        float al0 = __expf(m0 - mn0), al1 = __expf(m1 - mn1);
        m0 = mn0; m1 = mn1;
        float rs0 = 0.f, rs1 = 0.f;
#pragma unroll
        for (int n = 0; n < 8; n++) {
            sacc[n][0] = __expf(sacc[n][0] - mn0);
            sacc[n][1] = __expf(sacc[n][1] - mn0);
            sacc[n][2] = __expf(sacc[n][2] - mn1);
            sacc[n][3] = __expf(sacc[n][3] - mn1);
            rs0 += sacc[n][0] + sacc[n][1];
            rs1 += sacc[n][2] + sacc[n][3];
        }
        rs0 += __shfl_xor_sync(0xffffffffu, rs0, 1);
        rs0 += __shfl_xor_sync(0xffffffffu, rs0, 2);
        rs1 += __shfl_xor_sync(0xffffffffu, rs1, 1);
        rs1 += __shfl_xor_sync(0xffffffffu, rs1, 2);
        l0 = l0 * al0 + rs0;
        l1 = l1 * al1 + rs1;
#pragma unroll
        for (int nf = 0; nf < 16; nf++) {
            of[nf][0] *= al0; of[nf][1] *= al0;
            of[nf][2] *= al1; of[nf][3] *= al1;
        }

#pragma unroll
        for (int kc = 0; kc < 4; kc++) {
            uint32_t aph[4], apl[4];
            const int n0 = 2 * kc, n1 = 2 * kc + 1;
            float h00 = __bfloat162float(__float2bfloat16(sacc[n0][0]));
            float h01 = __bfloat162float(__float2bfloat16(sacc[n0][1]));
            float h02 = __bfloat162float(__float2bfloat16(sacc[n0][2]));
            float h03 = __bfloat162float(__float2bfloat16(sacc[n0][3]));
            float h10 = __bfloat162float(__float2bfloat16(sacc[n1][0]));
            float h11 = __bfloat162float(__float2bfloat16(sacc[n1][1]));
            float h12 = __bfloat162float(__float2bfloat16(sacc[n1][2]));
            float h13 = __bfloat162float(__float2bfloat16(sacc[n1][3]));
            aph[0] = pack_bf2(h00, h01); aph[1] = pack_bf2(h02, h03);
            aph[2] = pack_bf2(h10, h11); aph[3] = pack_bf2(h12, h13);
            apl[0] = pack_bf2(sacc[n0][0] - h00, sacc[n0][1] - h01);
            apl[1] = pack_bf2(sacc[n0][2] - h02, sacc[n0][3] - h03);
            apl[2] = pack_bf2(sacc[n1][0] - h10, sacc[n1][1] - h11);
            apl[3] = pack_bf2(sacc[n1][2] - h12, sacc[n1][3] - h13);
#pragma unroll
            for (int f = 0; f < 8; f++) {
                int s = 2 * f + (lane >> 4);
                uint32_t voff = (s >> 3) * 8192 +
                    swz((uint32_t)((kc * 16 + (lane & 15)) * 128 + (s & 7) * 16));
                uint32_t vh[4], vl[4];
                ldmx4t(vh, VHI + voff);
                ldmx4t(vl, VLO + voff);
                mma16816(of[2 * f],     aph, vh);
                mma16816(of[2 * f],     apl, vh);
                mma16816(of[2 * f],     aph, vl);
                mma16816(of[2 * f + 1], aph, vh + 2);
                mma16816(of[2 * f + 1], apl, vh + 2);
                mma16816(of[2 * f + 1], aph, vl + 2);
            }
        }

        __syncthreads();
        if (kt + 2 < ktiles) load_kv(kt + 2, kt & 1);
        else asm volatile("cp.async.commit_group;" ::: "memory");
    }

    // epilogue: ctx -> fp16 split (exact pair), token-major [t][h*HD+d]
    const int b_ = bh >> 5, h = bh & 31;
    const float inv0 = 1.f / l0, inv1 = 1.f / l1;
    const int row0 = q0 + wid * 16 + (lane >> 2);
    const size_t ob0 = ((size_t)(b_ * S_ + row0)) * H_ + h * HD_;
    const size_t ob1 = ((size_t)(b_ * S_ + row0 + 8)) * H_ + h * HD_;
#pragma unroll
    for (int nf = 0; nf < 16; nf++) {
        int d = nf * 8 + (lane & 3) * 2;
        split_store_h(g_Chi, g_Clo, ob0 + d, of[nf][0] * inv0, of[nf][1] * inv0);
        split_store_h(g_Chi, g_Clo, ob1 + d, of[nf][2] * inv1, of[nf][3] * inv1);
    }
}

// ---------------------------------------------------------------------------
extern "C" void kernel_launch(void* const* d_in, const int* in_sizes, int n_in,
                              void* d_out, int out_size)
{
    const float* hidden = (const float*)d_in[0];
    const float* w_attn = (const float*)d_in[1];
    const float* b_attn = (const float*)d_in[2];
    const float* w_proj = (const float*)d_in[3];
    const float* b_proj = (const float*)d_in[4];
    const float* cosb   = (const float*)d_in[5];
    const float* sinb   = (const float*)d_in[6];
    const float* logn   = (const float*)d_in[7];
    float* out = (float*)d_out;

    __half *ahi, *alo, *wh, *ph, *chi, *clo;
    cudaGetSymbolAddress((void**)&ahi, g_Ahi); cudaGetSymbolAddress((void**)&alo, g_Alo);
    cudaGetSymbolAddress((void**)&wh,  g_Wh);  cudaGetSymbolAddress((void**)&ph,  g_Ph);
    cudaGetSymbolAddress((void**)&chi, g_Chi); cudaGetSymbolAddress((void**)&clo, g_Clo);

    // 1) conversions: hidden -> fp16 hi/lo; weights -> fp16 single
    {
        int n1 = T_ * H_;   f32_split_h<<<n1 / 1024, 256>>>(hidden, ahi, alo, n1);
        int n2 = N3_ * H_;  f32_to_h<<<n2 / 1024, 256>>>(w_attn, wh, n2);
        int n3 = H_ * H_;   f32_to_h<<<n3 / 1024, 256>>>(w_proj, ph, n3);
    }

    const int gsmem = STAGES * STAGE_B;  // 98304 -> 2 CTAs/SM
    cudaFuncSetAttribute(gemm_mma, cudaFuncAttributeMaxDynamicSharedMemorySize, gsmem);

    // 2) QKV GEMM (fp16 2-term) fused bias+RoPE+logn, writes bf16-split Q/K/V
    gemm_mma<<<dim3(N3_ / 128, T_ / 64), 256, gsmem>>>(
        ahi, alo, wh, H_, 0, b_attn, cosb, sinb, logn, nullptr, 0);

    // 3) tensor-core causal flash attention (bf16 3-term), writes fp16-split ctx
    const int asmem = 65536 + 2 * 65536;  // 192KB
    cudaFuncSetAttribute(attn_mma, cudaFuncAttributeMaxDynamicSharedMemorySize, asmem);
    attn_mma<<<dim3(S_ / 128, B_ * NH_), 256, asmem>>>();

    // 4) output projection (fp16 2-term) + bias
    gemm_mma<<<dim3(H_ / 128, T_ / 64), 256, gsmem>>>(
        chi, clo, ph, H_, 1, b_proj, nullptr, nullptr, nullptr, out, H_);
}